// round 3
// baseline (speedup 1.0000x reference)
#include <cuda_runtime.h>
#include <math.h>

#define NH 8
#define TS 128
#define DH 64
#define DM 512

// ---------------- scratch (static device memory; no allocations) ----------------
__device__ float g_k1[2*NH*TS*DH];
__device__ float g_k2[2*NH*TS*DH];
__device__ float g_q [2*NH*TS*DH];
__device__ float g_va[2*NH*TS*DH];
__device__ float g_vb[2*NH*TS*DH];
__device__ float g_z [2*NH*TS*DH];

// Fast exp: scores are tiny (|x| << 1); Taylor deg-8 on |x|<=0.9 (rel err ~1e-6),
// exact expf fallback otherwise. Keeps exp off the MUFU pipe.
__device__ __forceinline__ float fast_exp(float x) {
    if (fabsf(x) > 0.9f) return expf(x);
    float r = 1.f/40320.f;
    r = r*x + 1.f/5040.f;
    r = r*x + 1.f/720.f;
    r = r*x + 1.f/120.f;
    r = r*x + 1.f/24.f;
    r = r*x + 1.f/6.f;
    r = r*x + 0.5f;
    r = r*x + 1.f;
    r = r*x + 1.f;
    return r;
}

// ---------------- kernel 1: five projections  out[b,n,p,h] = x[b,p,:] @ W[n,:,h] + bias --------
// grid (10, 8, 2): blockIdx.x = proj*2 + ptile ; block computes [64p x 64h], K=512.
__global__ void proj_kernel(const float* __restrict__ x,
                            const float* __restrict__ Wk1, const float* __restrict__ Wk2,
                            const float* __restrict__ Wq,  const float* __restrict__ Wv12,
                            const float* __restrict__ bk1, const float* __restrict__ bk2,
                            const float* __restrict__ bq)
{
    __shared__ __align__(16) float xs[64*33];
    __shared__ __align__(16) float ws[32*68];
    int tid = threadIdx.x;
    int px = blockIdx.x;
    int n  = blockIdx.y;
    int b  = blockIdx.z;
    int proj = px >> 1;
    int p0 = (px & 1) * 64;

    const float* W; const float* bias; float* dst;
    if (proj == 0)      { W = Wk1 + n*DM*DH;            bias = bk1 + n*DH; dst = g_k1; }
    else if (proj == 1) { W = Wk2 + n*DM*DH;            bias = bk2 + n*DH; dst = g_k2; }
    else if (proj == 2) { W = Wq  + n*DM*DH;            bias = bq  + n*DH; dst = g_q;  }
    else if (proj == 3) { W = Wv12 + n*2*DM*DH;         bias = 0;          dst = g_va; }
    else                { W = Wv12 + n*2*DM*DH + DM*DH; bias = 0;          dst = g_vb; }

    const float* xb = x + b*TS*DM;
    int ty = tid >> 4, tx = tid & 15;
    float acc[4][4];
    #pragma unroll
    for (int p = 0; p < 4; p++)
        #pragma unroll
        for (int c = 0; c < 4; c++) acc[p][c] = 0.f;

    for (int k0 = 0; k0 < DM; k0 += 32) {
        #pragma unroll
        for (int r = 0; r < 8; r++) {
            int e = tid + r*256;
            int pp = e >> 5, kk = e & 31;
            xs[pp*33 + kk] = xb[(p0+pp)*DM + k0 + kk];
        }
        #pragma unroll
        for (int r = 0; r < 8; r++) {
            int e = tid + r*256;
            int kk = e >> 6, hh = e & 63;
            ws[kk*68 + hh] = W[(k0+kk)*DH + hh];
        }
        __syncthreads();
        #pragma unroll
        for (int k = 0; k < 32; k++) {
            float4 bv = *(const float4*)&ws[k*68 + tx*4];
            #pragma unroll
            for (int p = 0; p < 4; p++) {
                float a = xs[(ty*4+p)*33 + k];
                acc[p][0] += a*bv.x; acc[p][1] += a*bv.y;
                acc[p][2] += a*bv.z; acc[p][3] += a*bv.w;
            }
        }
        __syncthreads();
    }
    int bn = b*NH + n;
    #pragma unroll
    for (int p = 0; p < 4; p++) {
        int prow = p0 + ty*4 + p;
        float* o = dst + (bn*TS + prow)*DH + tx*4;
        #pragma unroll
        for (int c = 0; c < 4; c++) {
            float v = acc[p][c];
            if (bias) v += bias[tx*4 + c];
            o[c] = v;
        }
    }
}

// ---------------- kernel 2: per (b,n,q): E=exp(S/64) for s<t<q, fused z output ----------------
// grid (128, 8, 2), 256 threads, dynamic smem. Produces g_z directly (rowA/colB/den in smem).
__global__ void attn_kernel(const float* __restrict__ bv12)
{
    extern __shared__ __align__(16) float sm[];
    float* su  = sm;                 // 128 x 68 (phase1: u = q*k1 ; phase2: va), float4 stride 17
    float* sk2 = su + 128*68;        // 128 x 68 (phase1: k2 ; phase2: vb)
    float* sE  = sk2 + 128*68;       // 128 x 132 (float4 stride 33) -- NOT zero-filled
    float* sqv = sE + 128*132;       // 64 (q vec; slot 0 reused for den later)
    float* srA = sqv + 64;           // 128 row sums
    float* scB = srA + 128;          // 128 col sums
    float* sred= scB + 128;          // 256 z partials

    int tid = threadIdx.x;
    int Q = blockIdx.x, n = blockIdx.y, b = blockIdx.z;
    int bn = b*NH + n;

    if (Q < 2) {                     // empty softmax -> all mass on sink -> z = 0
        if (tid < DH) g_z[(bn*TS + Q)*DH + tid] = 0.f;
        return;
    }

    const float4* gq4 = (const float4*)(g_q + (bn*TS + Q)*DH);
    if (tid < 16) ((float4*)sqv)[tid] = gq4[tid];
    __syncthreads();

    const float4* gk14 = (const float4*)(g_k1 + bn*TS*DH);
    const float4* gk24 = (const float4*)(g_k2 + bn*TS*DH);
    float4* su4  = (float4*)su;
    float4* sk24 = (float4*)sk2;
    float4* sE4  = (float4*)sE;

    int nload = Q * 16;
    for (int e = tid; e < nload; e += 256) {
        int s = e >> 4, h4 = e & 15;
        float4 qv = ((float4*)sqv)[h4];
        float4 a = gk14[s*16 + h4];
        a.x *= qv.x; a.y *= qv.y; a.z *= qv.z; a.w *= qv.w;
        su4 [s*17 + h4] = a;
        sk24[s*17 + h4] = gk24[s*16 + h4];
    }
    __syncthreads();

    int T = (Q + 3) >> 2;
    int ntiles = T*(T+1)/2;
    const float inv = 1.f/64.f;

    for (int tile = tid; tile < ntiles; tile += 256) {
        // decode lower-triangular tile index (i <= j)
        int j = (int)((sqrtf(8.f*(float)tile + 1.f) - 1.f) * 0.5f);
        while ((j+1)*(j+2)/2 <= tile) j++;
        while (j*(j+1)/2 > tile) j--;
        int i = tile - j*(j+1)/2;

        const float4* ua = su4  + i*4*17;
        const float4* kb = sk24 + j*4*17;
        float acc[4][4];
        #pragma unroll
        for (int p = 0; p < 4; p++)
            #pragma unroll
            for (int r = 0; r < 4; r++) acc[p][r] = 0.f;

        #pragma unroll
        for (int h4 = 0; h4 < 16; h4++) {
            float4 av[4], bv[4];
            av[0] = ua[h4]; av[1] = ua[17+h4]; av[2] = ua[34+h4]; av[3] = ua[51+h4];
            bv[0] = kb[h4]; bv[1] = kb[17+h4]; bv[2] = kb[34+h4]; bv[3] = kb[51+h4];
            #pragma unroll
            for (int p = 0; p < 4; p++)
                #pragma unroll
                for (int r = 0; r < 4; r++)
                    acc[p][r] += av[p].x*bv[r].x + av[p].y*bv[r].y
                               + av[p].z*bv[r].z + av[p].w*bv[r].w;
        }
        int s0 = i*4, t0 = j*4;
        #pragma unroll
        for (int p = 0; p < 4; p++) {
            int s = s0 + p;
            float4 ev;
            ev.x = (s < t0   && t0   < Q) ? fast_exp(acc[p][0] * inv) : 0.f;
            ev.y = (s < t0+1 && t0+1 < Q) ? fast_exp(acc[p][1] * inv) : 0.f;
            ev.z = (s < t0+2 && t0+2 < Q) ? fast_exp(acc[p][2] * inv) : 0.f;
            ev.w = (s < t0+3 && t0+3 < Q) ? fast_exp(acc[p][3] * inv) : 0.f;
            sE4[s*33 + j] = ev;   // masked entries stored as 0 -> no zero-fill needed
        }
    }
    __syncthreads();

    // reductions: rows read [4*(s/4), 4T) (all tile-written); cols read [0, 4*(t/4)+4)
    if (tid < 128) {
        int s = tid;
        int i = s >> 2;
        float sum = 0.f;
        const float4* row = (const float4*)(sE + s*132);
        for (int w = i; w < T; w++) { float4 v = row[w]; sum += v.x + v.y + v.z + v.w; }
        srA[s] = sum;            // s >= 4T -> empty loop -> 0
    } else {
        int t = tid - 128;
        float sum = 0.f;
        if (t < Q) {
            int send = (t >> 2)*4 + 4;
            for (int s = 0; s < send; s++) sum += sE[s*132 + t];
        }
        scB[t] = sum;
    }
    __syncthreads();

    if (tid < 32) {
        float v = srA[tid] + srA[tid+32] + srA[tid+64] + srA[tid+96];
        #pragma unroll
        for (int o = 16; o > 0; o >>= 1) v += __shfl_down_sync(0xffffffffu, v, o);
        if (tid == 0) sqv[0] = v;    // den (sink exp underflows to 0)
    }
    // overwrite su/sk2 with va/vb rows < Q (tile phase is done)
    {
        const float4* gva4 = (const float4*)(g_va + bn*TS*DH);
        const float4* gvb4 = (const float4*)(g_vb + bn*TS*DH);
        for (int e = tid; e < nload; e += 256) {
            int s = e >> 4, h4 = e & 15;
            su4 [s*17 + h4] = gva4[s*16 + h4];
            sk24[s*17 + h4] = gvb4[s*16 + h4];
        }
    }
    __syncthreads();

    // z[h] = (sum_s srA[s]*va[s,h] + sum_t scB[t]*vb[t,h]) / den + b_V12
    {
        int part = tid >> 6;            // 0..3, s-chunk of 32
        int h = tid & 63;
        int s0 = part*32;
        int s1 = s0 + 32; if (s1 > Q) s1 = Q;
        float acc = 0.f;
        for (int s = s0; s < s1; s++) {
            acc += srA[s]*su[s*68 + h] + scB[s]*sk2[s*68 + h];
        }
        sred[tid] = acc;
    }
    __syncthreads();
    if (tid < DH) {
        float tot = sred[tid] + sred[64+tid] + sred[128+tid] + sred[192+tid];
        float den = sqv[0];
        g_z[(bn*TS + Q)*DH + tid] = tot/den + bv12[n*DH + tid];
    }
}

// ---------------- kernel 3: out[b,p,d] = sum_{n,h} z[b,n,p,h] * W_O[n,h,d] + b_O ----------------
// grid (4, 16, 2): [32p x 32d] tile per block, 128 threads, thread = 2p x 4d.
__global__ void out_kernel(const float* __restrict__ Wo, const float* __restrict__ bo,
                           float* __restrict__ out)
{
    __shared__ __align__(16) float zs[32*68];
    __shared__ __align__(16) float ws[64*36];
    int tid = threadIdx.x;
    int p0 = blockIdx.x * 32, d0 = blockIdx.y * 32, b = blockIdx.z;
    int ty = tid >> 3;              // 0..15 -> rows 2ty, 2ty+1
    int tx = tid & 7;               // 0..7  -> d = d0 + tx*4
    float4* zs4 = (float4*)zs;
    float4* ws4 = (float4*)ws;

    float acc[2][4];
    #pragma unroll
    for (int r = 0; r < 2; r++)
        #pragma unroll
        for (int c = 0; c < 4; c++) acc[r][c] = 0.f;

    for (int n = 0; n < NH; n++) {
        const float4* gz4 = (const float4*)(g_z + ((b*NH + n)*TS + p0)*DH);
        #pragma unroll
        for (int r = 0; r < 4; r++) {
            int e = tid + r*128;            // 512 float4: 32p x 16h4
            int p = e >> 4, h4 = e & 15;
            zs4[p*17 + h4] = gz4[p*16 + h4];
        }
        const float* Wn = Wo + n*DH*DM;
        #pragma unroll
        for (int r = 0; r < 4; r++) {
            int e = tid + r*128;            // 512 float4: 64h x 8d4
            int h = e >> 3, d4 = e & 7;
            ws4[h*9 + d4] = *(const float4*)&Wn[h*DM + d0 + d4*4];
        }
        __syncthreads();
        #pragma unroll
        for (int h = 0; h < 64; h++) {
            float4 w = ws4[h*9 + tx];
            float a0 = zs[(ty*2)*68 + h];
            float a1 = zs[(ty*2+1)*68 + h];
            acc[0][0] += a0*w.x; acc[0][1] += a0*w.y; acc[0][2] += a0*w.z; acc[0][3] += a0*w.w;
            acc[1][0] += a1*w.x; acc[1][1] += a1*w.y; acc[1][2] += a1*w.z; acc[1][3] += a1*w.w;
        }
        __syncthreads();
    }
    #pragma unroll
    for (int r = 0; r < 2; r++) {
        int p = p0 + ty*2 + r;
        float* o = out + b*TS*DM + p*DM + d0 + tx*4;
        #pragma unroll
        for (int c = 0; c < 4; c++) o[c] = acc[r][c] + bo[d0 + tx*4 + c];
    }
}

// ---------------- launch ----------------
extern "C" void kernel_launch(void* const* d_in, const int* in_sizes, int n_in,
                              void* d_out, int out_size)
{
    const float* x    = (const float*)d_in[0];
    const float* Wk1  = (const float*)d_in[1];
    const float* Wk2  = (const float*)d_in[2];
    const float* Wq   = (const float*)d_in[3];
    const float* Wv12 = (const float*)d_in[4];
    const float* Wo   = (const float*)d_in[5];
    const float* bk1  = (const float*)d_in[6];
    const float* bk2  = (const float*)d_in[7];
    const float* bq   = (const float*)d_in[8];
    const float* bv12 = (const float*)d_in[9];
    const float* bo   = (const float*)d_in[10];
    float* out = (float*)d_out;

    proj_kernel<<<dim3(10, 8, 2), 256>>>(x, Wk1, Wk2, Wq, Wv12, bk1, bk2, bq);

    int smem2 = (128*68*2 + 128*132 + 64 + 128 + 128 + 256) * (int)sizeof(float);  // ~136.3 KB
    cudaFuncSetAttribute(attn_kernel, cudaFuncAttributeMaxDynamicSharedMemorySize, smem2);
    attn_kernel<<<dim3(128, 8, 2), 256, smem2>>>(bv12);

    out_kernel<<<dim3(4, 16, 2), 128>>>(Wo, bo, out);
}

// round 7
// speedup vs baseline: 2.0245x; 2.0245x over previous
#include <cuda_runtime.h>
#include <math.h>

#define NH 8
#define TS 128
#define DH 64
#define DM 512

// ---------------- scratch (static device memory; no allocations) ----------------
__device__ float g_k1[2*NH*TS*DH];
__device__ float g_k2[2*NH*TS*DH];
__device__ float g_q [2*NH*TS*DH];
__device__ float g_va[2*NH*TS*DH];
__device__ float g_vb[2*NH*TS*DH];
__device__ float g_z [2*NH*TS*DH];

// Fast exp: scores are tiny (|x| << 1); Taylor deg-8 on |x|<=0.9 (rel err ~1e-6),
// exact expf fallback otherwise (never hit on real data; stale rows are zero-filled).
__device__ __forceinline__ float fast_exp(float x) {
    if (fabsf(x) > 0.9f) return expf(x);
    float r = 1.f/40320.f;
    r = r*x + 1.f/5040.f;
    r = r*x + 1.f/720.f;
    r = r*x + 1.f/120.f;
    r = r*x + 1.f/24.f;
    r = r*x + 1.f/6.f;
    r = r*x + 0.5f;
    r = r*x + 1.f;
    r = r*x + 1.f;
    return r;
}

// ---------------- kernel 1: five projections  out[b,n,p,h] = x[b,p,:] @ W[n,:,h] + bias --------
// grid (20, 8, 2): blockIdx.x = proj*4 + ptile ; block computes [32p x 64h], K=512, 128 threads.
__global__ void proj_kernel(const float* __restrict__ x,
                            const float* __restrict__ Wk1, const float* __restrict__ Wk2,
                            const float* __restrict__ Wq,  const float* __restrict__ Wv12,
                            const float* __restrict__ bk1, const float* __restrict__ bk2,
                            const float* __restrict__ bq)
{
    __shared__ __align__(16) float xs[32*33];
    __shared__ __align__(16) float ws[32*68];
    int tid = threadIdx.x;
    int px = blockIdx.x;
    int n  = blockIdx.y;
    int b  = blockIdx.z;
    int proj = px >> 2;
    int p0 = (px & 3) * 32;

    const float* W; const float* bias; float* dst;
    if (proj == 0)      { W = Wk1 + n*DM*DH;            bias = bk1 + n*DH; dst = g_k1; }
    else if (proj == 1) { W = Wk2 + n*DM*DH;            bias = bk2 + n*DH; dst = g_k2; }
    else if (proj == 2) { W = Wq  + n*DM*DH;            bias = bq  + n*DH; dst = g_q;  }
    else if (proj == 3) { W = Wv12 + n*2*DM*DH;         bias = 0;          dst = g_va; }
    else                { W = Wv12 + n*2*DM*DH + DM*DH; bias = 0;          dst = g_vb; }

    const float* xb = x + b*TS*DM;
    int ty = tid >> 4, tx = tid & 15;      // 8 x 16 threads -> 4p x 4h each
    float acc[4][4];
    #pragma unroll
    for (int p = 0; p < 4; p++)
        #pragma unroll
        for (int c = 0; c < 4; c++) acc[p][c] = 0.f;

    for (int k0 = 0; k0 < DM; k0 += 32) {
        #pragma unroll
        for (int r = 0; r < 8; r++) {
            int e = tid + r*128;           // 1024 elems: 32p x 32k
            int pp = e >> 5, kk = e & 31;
            xs[pp*33 + kk] = xb[(p0+pp)*DM + k0 + kk];
        }
        #pragma unroll
        for (int r = 0; r < 16; r++) {
            int e = tid + r*128;           // 2048 elems: 32k x 64h
            int kk = e >> 6, hh = e & 63;
            ws[kk*68 + hh] = W[(k0+kk)*DH + hh];
        }
        __syncthreads();
        #pragma unroll
        for (int k = 0; k < 32; k++) {
            float4 bv = *(const float4*)&ws[k*68 + tx*4];
            #pragma unroll
            for (int p = 0; p < 4; p++) {
                float a = xs[(ty*4+p)*33 + k];
                acc[p][0] += a*bv.x; acc[p][1] += a*bv.y;
                acc[p][2] += a*bv.z; acc[p][3] += a*bv.w;
            }
        }
        __syncthreads();
    }
    int bn = b*NH + n;
    #pragma unroll
    for (int p = 0; p < 4; p++) {
        int prow = p0 + ty*4 + p;
        float* o = dst + (bn*TS + prow)*DH + tx*4;
        #pragma unroll
        for (int c = 0; c < 4; c++) {
            float v = acc[p][c];
            if (bias) v += bias[tx*4 + c];
            o[c] = v;
        }
    }
}

// ---------------- kernel 2: per (b,n,q): tiles reduce in-register, fused z output ----------------
// grid (128, 8, 2), 256 threads. 4x8 score tiles -> 12-float partials -> rowA/colB -> z.
// No full E tile in smem -> ~85KB -> 2 blocks/SM.
#define MAXTILES 272
__global__ __launch_bounds__(256, 2) void attn_kernel(const float* __restrict__ bv12)
{
    extern __shared__ __align__(16) float sm[];
    float* su    = sm;                    // 128 x 68 (phase1: k1*q ; phase2: va)
    float* sk2   = su   + 128*68;         // 128 x 68 (phase1: k2   ; phase2: vb)
    float* spart = sk2  + 128*68;         // MAXTILES x 12 (row[4], col[8] partials)
    float* srA   = spart + MAXTILES*12;   // 128 row sums
    float* scB   = srA  + 128;            // 128 col sums
    float* sred  = scB  + 128;            // 256 z partials
    float* sqv   = sred + 256;            // 64 q-vector
    int*   soff  = (int*)(sqv + 64);      // 17 tile-row offsets
    float* sden  = (float*)(soff + 18);   // 1

    int tid = threadIdx.x;
    int Q = blockIdx.x, n = blockIdx.y, b = blockIdx.z;
    int bn = b*NH + n;

    if (Q < 2) {                          // empty softmax -> all mass on sink -> z = 0
        if (tid < DH) g_z[(bn*TS + Q)*DH + tid] = 0.f;
        return;
    }

    int T4 = (Q + 3) >> 2;                // 4-row s tiles
    int T8 = (Q + 7) >> 3;                // 8-col t tiles

    const float4* gq4 = (const float4*)(g_q + (bn*TS + Q)*DH);
    if (tid < 16) ((float4*)sqv)[tid] = gq4[tid];
    // tile-offset table: cnt(j) = min(T4, 2j+2); soff[j] = prefix sum
    if (tid >= 32 && tid <= 32 + T8) {
        int j = tid - 32, o = 0;
        for (int jj = 0; jj < j; jj++) { int c = 2*jj + 2; if (c > T4) c = T4; o += c; }
        soff[j] = o;
    }
    __syncthreads();

    int ntiles = soff[T8];
    const float4* gk14 = (const float4*)(g_k1 + bn*TS*DH);
    const float4* gk24 = (const float4*)(g_k2 + bn*TS*DH);
    float4* su4  = (float4*)su;
    float4* sk24 = (float4*)sk2;

    int nload = Q * 16;
    for (int e = tid; e < nload; e += 256) {
        int s = e >> 4, h4 = e & 15;
        float4 qv = ((float4*)sqv)[h4];
        float4 a = gk14[s*16 + h4];
        a.x *= qv.x; a.y *= qv.y; a.z *= qv.z; a.w *= qv.w;
        su4 [s*17 + h4] = a;
        sk24[s*17 + h4] = gk24[s*16 + h4];
    }
    // zero-fill stale rows [Q, 8*T8) so tile math stays on the fast exp path
    int rmax = 8*T8;
    float4 zz = make_float4(0.f,0.f,0.f,0.f);
    for (int e = tid; e < (rmax - Q)*16; e += 256) {
        int s = Q + (e >> 4), h4 = e & 15;
        su4 [s*17 + h4] = zz;
        sk24[s*17 + h4] = zz;
    }
    __syncthreads();

    const float inv = 1.f/64.f;

    for (int tile = tid; tile < ntiles; tile += 256) {
        int j = 0;
        while (soff[j+1] <= tile) j++;
        int i = tile - soff[j];
        int s0 = i*4, t0 = j*8;

        const float4* ua = su4  + s0*17;
        const float4* kb = sk24 + t0*17;
        float acc[4][8];
        #pragma unroll
        for (int p = 0; p < 4; p++)
            #pragma unroll
            for (int r = 0; r < 8; r++) acc[p][r] = 0.f;

        #pragma unroll
        for (int h4 = 0; h4 < 16; h4++) {
            float4 av0 = ua[h4], av1 = ua[17+h4], av2 = ua[34+h4], av3 = ua[51+h4];
            #pragma unroll
            for (int r = 0; r < 8; r++) {
                float4 bv = kb[r*17 + h4];
                acc[0][r] += av0.x*bv.x + av0.y*bv.y + av0.z*bv.z + av0.w*bv.w;
                acc[1][r] += av1.x*bv.x + av1.y*bv.y + av1.z*bv.z + av1.w*bv.w;
                acc[2][r] += av2.x*bv.x + av2.y*bv.y + av2.z*bv.z + av2.w*bv.w;
                acc[3][r] += av3.x*bv.x + av3.y*bv.y + av3.z*bv.z + av3.w*bv.w;
            }
        }
        float rowp[4] = {0.f,0.f,0.f,0.f};
        float colp[8] = {0.f,0.f,0.f,0.f,0.f,0.f,0.f,0.f};
        #pragma unroll
        for (int p = 0; p < 4; p++) {
            int s = s0 + p;
            #pragma unroll
            for (int r = 0; r < 8; r++) {
                int t = t0 + r;
                float e = 0.f;
                if (s < t && t < Q) e = fast_exp(acc[p][r] * inv);
                rowp[p] += e; colp[r] += e;
            }
        }
        float* pp = spart + tile*12;
        *(float4*)(pp)     = make_float4(rowp[0], rowp[1], rowp[2], rowp[3]);
        *(float4*)(pp + 4) = make_float4(colp[0], colp[1], colp[2], colp[3]);
        *(float4*)(pp + 8) = make_float4(colp[4], colp[5], colp[6], colp[7]);
    }
    __syncthreads();

    // reload su/sk2 with va/vb (tile phase done)
    {
        const float4* gva4 = (const float4*)(g_va + bn*TS*DH);
        const float4* gvb4 = (const float4*)(g_vb + bn*TS*DH);
        for (int e = tid; e < nload; e += 256) {
            int s = e >> 4, h4 = e & 15;
            su4 [s*17 + h4] = gva4[s*16 + h4];
            sk24[s*17 + h4] = gvb4[s*16 + h4];
        }
    }
    // deterministic row/col reduction from compact partials
    if (tid < 128) {
        int s = tid, i = s >> 2, c = s & 3;
        float sum = 0.f;
        if (i < T4) {
            for (int j = i >> 1; j < T8; j++)
                sum += spart[(soff[j] + i)*12 + c];
        }
        srA[s] = sum;
    } else {
        int t = tid - 128, j = t >> 3, r = t & 7;
        float sum = 0.f;
        if (t < 8*T8) {
            int cnt = soff[j+1] - soff[j];
            int base = soff[j]*12 + 4 + r;
            for (int i = 0; i < cnt; i++) sum += spart[base + i*12];
        }
        scB[t] = sum;
    }
    __syncthreads();

    // z partials: z[h] = sum_s srA[s]*va[s,h] + sum_t scB[t]*vb[t,h]
    {
        int part = tid >> 6;              // 0..3, s-chunk of 32
        int h = tid & 63;
        int s0 = part*32;
        int s1 = s0 + 32; if (s1 > Q) s1 = Q;
        float acc = 0.f;
        for (int s = s0; s < s1; s++)
            acc += srA[s]*su[s*68 + h] + scB[s]*sk2[s*68 + h];
        sred[tid] = acc;
    }
    __syncthreads();
    if (tid < 32) {
        float v = srA[tid] + srA[tid+32] + srA[tid+64] + srA[tid+96];
        #pragma unroll
        for (int o = 16; o > 0; o >>= 1) v += __shfl_down_sync(0xffffffffu, v, o);
        if (tid == 0) sden[0] = v;        // den (sink exp underflows to 0)
    }
    __syncthreads();
    if (tid < DH) {
        float tot = sred[tid] + sred[64+tid] + sred[128+tid] + sred[192+tid];
        g_z[(bn*TS + Q)*DH + tid] = tot/sden[0] + bv12[n*DH + tid];
    }
}

// ---------------- kernel 3: out[b,p,d] = sum_{n,h} z[b,n,p,h] * W_O[n,h,d] + b_O ----------------
// grid (4, 16, 2): [32p x 32d] tile per block, 128 threads, thread = 2p x 4d.
__global__ void out_kernel(const float* __restrict__ Wo, const float* __restrict__ bo,
                           float* __restrict__ out)
{
    __shared__ __align__(16) float zs[32*68];
    __shared__ __align__(16) float ws[64*36];
    int tid = threadIdx.x;
    int p0 = blockIdx.x * 32, d0 = blockIdx.y * 32, b = blockIdx.z;
    int ty = tid >> 3;              // 0..15 -> rows 2ty, 2ty+1
    int tx = tid & 7;               // 0..7  -> d = d0 + tx*4
    float4* zs4 = (float4*)zs;
    float4* ws4 = (float4*)ws;

    float acc[2][4];
    #pragma unroll
    for (int r = 0; r < 2; r++)
        #pragma unroll
        for (int c = 0; c < 4; c++) acc[r][c] = 0.f;

    for (int n = 0; n < NH; n++) {
        const float4* gz4 = (const float4*)(g_z + ((b*NH + n)*TS + p0)*DH);
        #pragma unroll
        for (int r = 0; r < 4; r++) {
            int e = tid + r*128;            // 512 float4: 32p x 16h4
            int p = e >> 4, h4 = e & 15;
            zs4[p*17 + h4] = gz4[p*16 + h4];
        }
        const float* Wn = Wo + n*DH*DM;
        #pragma unroll
        for (int r = 0; r < 4; r++) {
            int e = tid + r*128;            // 512 float4: 64h x 8d4
            int h = e >> 3, d4 = e & 7;
            ws4[h*9 + d4] = *(const float4*)&Wn[h*DM + d0 + d4*4];
        }
        __syncthreads();
        #pragma unroll
        for (int h = 0; h < 64; h++) {
            float4 w = ws4[h*9 + tx];
            float a0 = zs[(ty*2)*68 + h];
            float a1 = zs[(ty*2+1)*68 + h];
            acc[0][0] += a0*w.x; acc[0][1] += a0*w.y; acc[0][2] += a0*w.z; acc[0][3] += a0*w.w;
            acc[1][0] += a1*w.x; acc[1][1] += a1*w.y; acc[1][2] += a1*w.z; acc[1][3] += a1*w.w;
        }
        __syncthreads();
    }
    #pragma unroll
    for (int r = 0; r < 2; r++) {
        int p = p0 + ty*2 + r;
        float* o = out + b*TS*DM + p*DM + d0 + tx*4;
        #pragma unroll
        for (int c = 0; c < 4; c++) o[c] = acc[r][c] + bo[d0 + tx*4 + c];
    }
}

// ---------------- launch ----------------
extern "C" void kernel_launch(void* const* d_in, const int* in_sizes, int n_in,
                              void* d_out, int out_size)
{
    const float* x    = (const float*)d_in[0];
    const float* Wk1  = (const float*)d_in[1];
    const float* Wk2  = (const float*)d_in[2];
    const float* Wq   = (const float*)d_in[3];
    const float* Wv12 = (const float*)d_in[4];
    const float* Wo   = (const float*)d_in[5];
    const float* bk1  = (const float*)d_in[6];
    const float* bk2  = (const float*)d_in[7];
    const float* bq   = (const float*)d_in[8];
    const float* bv12 = (const float*)d_in[9];
    const float* bo   = (const float*)d_in[10];
    float* out = (float*)d_out;

    proj_kernel<<<dim3(20, 8, 2), 128>>>(x, Wk1, Wk2, Wq, Wv12, bk1, bk2, bq);

    int smem2 = (128*68*2 + MAXTILES*12 + 128 + 128 + 256 + 64)*(int)sizeof(float)
              + 18*(int)sizeof(int) + 8;   // ~85.2 KB -> 2 blocks/SM
    cudaFuncSetAttribute(attn_kernel, cudaFuncAttributeMaxDynamicSharedMemorySize, smem2);
    attn_kernel<<<dim3(128, 8, 2), 256, smem2>>>(bv12);

    out_kernel<<<dim3(4, 16, 2), 128>>>(Wo, bo, out);
}

// round 8
// speedup vs baseline: 2.1198x; 1.0471x over previous
#include <cuda_runtime.h>
#include <math.h>

#define NH 8
#define TS 128
#define DH 64
#define DM 512

// ---------------- scratch (static device memory; no allocations) ----------------
__device__ float g_k1[2*NH*TS*DH];
__device__ float g_k2[2*NH*TS*DH];
__device__ float g_q [2*NH*TS*DH];
__device__ float g_va[2*NH*TS*DH];
__device__ float g_vb[2*NH*TS*DH];
__device__ float g_z [2*NH*TS*DH];

// Fast exp: scores are tiny (|x| << 1); Taylor deg-8 on |x|<=0.9 (rel err ~1e-6),
// exact expf fallback otherwise (never hit on real data; stale rows are zero-filled).
__device__ __forceinline__ float fast_exp(float x) {
    if (fabsf(x) > 0.9f) return expf(x);
    float r = 1.f/40320.f;
    r = r*x + 1.f/5040.f;
    r = r*x + 1.f/720.f;
    r = r*x + 1.f/120.f;
    r = r*x + 1.f/24.f;
    r = r*x + 1.f/6.f;
    r = r*x + 0.5f;
    r = r*x + 1.f;
    r = r*x + 1.f;
    return r;
}

// ---------------- kernel 1: five projections  out[b,n,p,h] = x[b,p,:] @ W[n,:,h] + bias --------
// grid (20, 16, 2): x = proj*4 + ptile(32p), y = n*2 + hhalf(32h). 128 threads, thread=2p x 4h.
__global__ void proj_kernel(const float* __restrict__ x,
                            const float* __restrict__ Wk1, const float* __restrict__ Wk2,
                            const float* __restrict__ Wq,  const float* __restrict__ Wv12,
                            const float* __restrict__ bk1, const float* __restrict__ bk2,
                            const float* __restrict__ bq)
{
    __shared__ __align__(16) float xs[32*33];
    __shared__ __align__(16) float ws[32*36];
    int tid = threadIdx.x;
    int px = blockIdx.x;
    int ny = blockIdx.y;
    int b  = blockIdx.z;
    int proj = px >> 2;
    int p0 = (px & 3) * 32;
    int n  = ny >> 1;
    int h0 = (ny & 1) * 32;

    const float* W; const float* bias; float* dst;
    if (proj == 0)      { W = Wk1 + n*DM*DH;            bias = bk1 + n*DH; dst = g_k1; }
    else if (proj == 1) { W = Wk2 + n*DM*DH;            bias = bk2 + n*DH; dst = g_k2; }
    else if (proj == 2) { W = Wq  + n*DM*DH;            bias = bq  + n*DH; dst = g_q;  }
    else if (proj == 3) { W = Wv12 + n*2*DM*DH;         bias = 0;          dst = g_va; }
    else                { W = Wv12 + n*2*DM*DH + DM*DH; bias = 0;          dst = g_vb; }

    const float* xb = x + b*TS*DM;
    int ty = tid >> 3;                 // 0..15 -> p = p0 + ty*2 + {0,1}
    int tx = tid & 7;                  // 0..7  -> h = h0 + tx*4 ..+3
    float acc[2][4];
    #pragma unroll
    for (int r = 0; r < 2; r++)
        #pragma unroll
        for (int c = 0; c < 4; c++) acc[r][c] = 0.f;

    for (int k0 = 0; k0 < DM; k0 += 32) {
        #pragma unroll
        for (int r = 0; r < 8; r++) {
            int e = tid + r*128;           // 1024: 32p x 32k
            int pp = e >> 5, kk = e & 31;
            xs[pp*33 + kk] = xb[(p0+pp)*DM + k0 + kk];
        }
        #pragma unroll
        for (int r = 0; r < 8; r++) {
            int e = tid + r*128;           // 1024: 32k x 32h
            int kk = e >> 5, hh = e & 31;
            ws[kk*36 + hh] = W[(k0+kk)*DH + h0 + hh];
        }
        __syncthreads();
        #pragma unroll
        for (int k = 0; k < 32; k++) {
            float4 bv = *(const float4*)&ws[k*36 + tx*4];
            float a0 = xs[(ty*2  )*33 + k];
            float a1 = xs[(ty*2+1)*33 + k];
            acc[0][0] += a0*bv.x; acc[0][1] += a0*bv.y; acc[0][2] += a0*bv.z; acc[0][3] += a0*bv.w;
            acc[1][0] += a1*bv.x; acc[1][1] += a1*bv.y; acc[1][2] += a1*bv.z; acc[1][3] += a1*bv.w;
        }
        __syncthreads();
    }
    int bn = b*NH + n;
    #pragma unroll
    for (int r = 0; r < 2; r++) {
        int prow = p0 + ty*2 + r;
        float* o = dst + (bn*TS + prow)*DH + h0 + tx*4;
        #pragma unroll
        for (int c = 0; c < 4; c++) {
            float v = acc[r][c];
            if (bias) v += bias[h0 + tx*4 + c];
            o[c] = v;
        }
    }
}

// ---------------- kernel 2: per (b,n,q): warp-cooperative 8x8 score tiles, fused z ----------------
// grid (128, 8, 2), 256 threads = 8 warps. Tile (i,j): i<=j, ntiles = T8(T8+1)/2 (closed form).
// Lane (p,r) = (lane>>3, lane&7): rows {s0+p, s0+p+4}, col t0+r. Conflict-free broadcast LDS.
#define MAXT 136
__global__ __launch_bounds__(256, 2) void attn_kernel(const float* __restrict__ bv12)
{
    extern __shared__ __align__(16) float sm[];
    float* su    = sm;                    // 128 x 68 (phase1: k1*q ; phase2: va)
    float* sk2   = su   + 128*68;         // 128 x 68 (phase1: k2   ; phase2: vb)
    float* spart = sk2  + 128*68;         // MAXT x 16 (row[8], col[8] per tile)
    float* srA   = spart + MAXT*16;       // 128 row sums
    float* scB   = srA  + 128;            // 128 col sums
    float* sred  = scB  + 128;            // 256 z partials
    float* sqv   = sred + 256;            // 64 q-vector
    float* sden  = sqv  + 64;             // 1

    int tid = threadIdx.x;
    int wid = tid >> 5, lane = tid & 31;
    int p = lane >> 3, r = lane & 7;
    int Q = blockIdx.x, n = blockIdx.y, b = blockIdx.z;
    int bn = b*NH + n;

    if (Q < 2) {                          // empty softmax -> all mass on sink -> z = 0
        if (tid < DH) g_z[(bn*TS + Q)*DH + tid] = 0.f;
        return;
    }

    int T8 = (Q + 7) >> 3;
    int ntiles = T8*(T8+1)/2;

    const float4* gq4 = (const float4*)(g_q + (bn*TS + Q)*DH);
    if (tid < 16) ((float4*)sqv)[tid] = gq4[tid];
    __syncthreads();

    const float4* gk14 = (const float4*)(g_k1 + bn*TS*DH);
    const float4* gk24 = (const float4*)(g_k2 + bn*TS*DH);
    float4* su4  = (float4*)su;
    float4* sk24 = (float4*)sk2;

    int nload = Q * 16;
    for (int e = tid; e < nload; e += 256) {
        int s = e >> 4, h4 = e & 15;
        float4 qv = ((float4*)sqv)[h4];
        float4 a = gk14[s*16 + h4];
        a.x *= qv.x; a.y *= qv.y; a.z *= qv.z; a.w *= qv.w;
        su4 [s*17 + h4] = a;
        sk24[s*17 + h4] = gk24[s*16 + h4];
    }
    // zero-fill stale rows [Q, 8*T8) so tile math stays on the fast exp path
    int rmax = 8*T8;
    float4 zz = make_float4(0.f,0.f,0.f,0.f);
    for (int e = tid; e < (rmax - Q)*16; e += 256) {
        int s = Q + (e >> 4), h4 = e & 15;
        su4 [s*17 + h4] = zz;
        sk24[s*17 + h4] = zz;
    }
    __syncthreads();

    const float inv = 1.f/64.f;

    for (int tile = wid; tile < ntiles; tile += 8) {
        // decode tile -> (i, j), i <= j, offset j(j+1)/2 (warp-uniform)
        int j = (int)((sqrtf(8.f*(float)tile + 1.f) - 1.f) * 0.5f);
        while ((j+1)*(j+2)/2 <= tile) j++;
        while (j*(j+1)/2 > tile) j--;
        int i = tile - j*(j+1)/2;
        int s0 = i*8, t0 = j*8;

        const float4* ua = su4  + (s0+p)*17;      // 4 distinct rows, 8-way bcast
        const float4* ub = su4  + (s0+p+4)*17;
        const float4* kb = sk24 + (t0+r)*17;      // 8 distinct rows, 4-way bcast
        float acc0 = 0.f, acc1 = 0.f;
        #pragma unroll
        for (int h4 = 0; h4 < 16; h4++) {
            float4 bv = kb[h4];
            float4 a0 = ua[h4];
            float4 a1 = ub[h4];
            acc0 += a0.x*bv.x + a0.y*bv.y + a0.z*bv.z + a0.w*bv.w;
            acc1 += a1.x*bv.x + a1.y*bv.y + a1.z*bv.z + a1.w*bv.w;
        }
        int sa = s0 + p, sb = s0 + p + 4, t = t0 + r;
        float e0 = (sa < t && t < Q) ? fast_exp(acc0 * inv) : 0.f;
        float e1 = (sb < t && t < Q) ? fast_exp(acc1 * inv) : 0.f;

        // row sums: reduce over r (8 lanes, same p)
        float r0 = e0, r1 = e1;
        r0 += __shfl_down_sync(0xffffffffu, r0, 4);
        r0 += __shfl_down_sync(0xffffffffu, r0, 2);
        r0 += __shfl_down_sync(0xffffffffu, r0, 1);
        r1 += __shfl_down_sync(0xffffffffu, r1, 4);
        r1 += __shfl_down_sync(0xffffffffu, r1, 2);
        r1 += __shfl_down_sync(0xffffffffu, r1, 1);
        // col sums: reduce over p (4 lanes, stride 8); both sub-rows contribute
        float c = e0 + e1;
        c += __shfl_down_sync(0xffffffffu, c, 16);
        c += __shfl_down_sync(0xffffffffu, c, 8);

        float* pp = spart + tile*16;
        if (r == 0) { pp[p] = r0; pp[p+4] = r1; }
        if (lane < 8) pp[8 + lane] = c;
    }
    __syncthreads();

    // reload su/sk2 with va/vb (tile phase done)
    {
        const float4* gva4 = (const float4*)(g_va + bn*TS*DH);
        const float4* gvb4 = (const float4*)(g_vb + bn*TS*DH);
        for (int e = tid; e < nload; e += 256) {
            int s = e >> 4, h4 = e & 15;
            su4 [s*17 + h4] = gva4[s*16 + h4];
            sk24[s*17 + h4] = gvb4[s*16 + h4];
        }
    }
    // deterministic row/col reduction over compact tile partials
    if (tid < 128) {
        int s = tid, i = s >> 3, pr = s & 7;
        float sum = 0.f;
        if (i < T8) {
            for (int j = i; j < T8; j++)
                sum += spart[(j*(j+1)/2 + i)*16 + pr];
        }
        srA[s] = sum;
    } else {
        int t = tid - 128, j = t >> 3, rr = t & 7;
        float sum = 0.f;
        if (j < T8) {
            int base = (j*(j+1)/2)*16 + 8 + rr;
            for (int i = 0; i <= j; i++) sum += spart[base + i*16];
        }
        scB[t] = sum;
    }
    __syncthreads();

    // z partials: z[h] = sum_s srA[s]*va[s,h] + sum_t scB[t]*vb[t,h]
    {
        int part = tid >> 6;              // 0..3, s-chunk of 32
        int h = tid & 63;
        int s0 = part*32;
        int s1 = s0 + 32; if (s1 > Q) s1 = Q;
        float acc = 0.f;
        for (int s = s0; s < s1; s++)
            acc += srA[s]*su[s*68 + h] + scB[s]*sk2[s*68 + h];
        sred[tid] = acc;
    }
    __syncthreads();
    if (tid < 32) {
        float v = srA[tid] + srA[tid+32] + srA[tid+64] + srA[tid+96];
        #pragma unroll
        for (int o = 16; o > 0; o >>= 1) v += __shfl_down_sync(0xffffffffu, v, o);
        if (tid == 0) sden[0] = v;        // den (sink exp underflows to 0)
    }
    __syncthreads();
    if (tid < DH) {
        float tot = sred[tid] + sred[64+tid] + sred[128+tid] + sred[192+tid];
        g_z[(bn*TS + Q)*DH + tid] = tot/sden[0] + bv12[n*DH + tid];
    }
}

// ---------------- kernel 3: out[b,p,d] = sum_{n,h} z[b,n,p,h] * W_O[n,h,d] + b_O ----------------
// grid (4, 16, 2): [32p x 32d] tile per block, 128 threads, thread = 2p x 4d.
__global__ void out_kernel(const float* __restrict__ Wo, const float* __restrict__ bo,
                           float* __restrict__ out)
{
    __shared__ __align__(16) float zs[32*68];
    __shared__ __align__(16) float ws[64*36];
    int tid = threadIdx.x;
    int p0 = blockIdx.x * 32, d0 = blockIdx.y * 32, b = blockIdx.z;
    int ty = tid >> 3;              // 0..15 -> rows 2ty, 2ty+1
    int tx = tid & 7;               // 0..7  -> d = d0 + tx*4
    float4* zs4 = (float4*)zs;
    float4* ws4 = (float4*)ws;

    float acc[2][4];
    #pragma unroll
    for (int r = 0; r < 2; r++)
        #pragma unroll
        for (int c = 0; c < 4; c++) acc[r][c] = 0.f;

    for (int n = 0; n < NH; n++) {
        const float4* gz4 = (const float4*)(g_z + ((b*NH + n)*TS + p0)*DH);
        #pragma unroll
        for (int r = 0; r < 4; r++) {
            int e = tid + r*128;            // 512 float4: 32p x 16h4
            int p = e >> 4, h4 = e & 15;
            zs4[p*17 + h4] = gz4[p*16 + h4];
        }
        const float* Wn = Wo + n*DH*DM;
        #pragma unroll
        for (int r = 0; r < 4; r++) {
            int e = tid + r*128;            // 512 float4: 64h x 8d4
            int h = e >> 3, d4 = e & 7;
            ws4[h*9 + d4] = *(const float4*)&Wn[h*DM + d0 + d4*4];
        }
        __syncthreads();
        #pragma unroll
        for (int h = 0; h < 64; h++) {
            float4 w = ws4[h*9 + tx];
            float a0 = zs[(ty*2)*68 + h];
            float a1 = zs[(ty*2+1)*68 + h];
            acc[0][0] += a0*w.x; acc[0][1] += a0*w.y; acc[0][2] += a0*w.z; acc[0][3] += a0*w.w;
            acc[1][0] += a1*w.x; acc[1][1] += a1*w.y; acc[1][2] += a1*w.z; acc[1][3] += a1*w.w;
        }
        __syncthreads();
    }
    #pragma unroll
    for (int r = 0; r < 2; r++) {
        int p = p0 + ty*2 + r;
        float* o = out + b*TS*DM + p*DM + d0 + tx*4;
        #pragma unroll
        for (int c = 0; c < 4; c++) o[c] = acc[r][c] + bo[d0 + tx*4 + c];
    }
}

// ---------------- launch ----------------
extern "C" void kernel_launch(void* const* d_in, const int* in_sizes, int n_in,
                              void* d_out, int out_size)
{
    const float* x    = (const float*)d_in[0];
    const float* Wk1  = (const float*)d_in[1];
    const float* Wk2  = (const float*)d_in[2];
    const float* Wq   = (const float*)d_in[3];
    const float* Wv12 = (const float*)d_in[4];
    const float* Wo   = (const float*)d_in[5];
    const float* bk1  = (const float*)d_in[6];
    const float* bk2  = (const float*)d_in[7];
    const float* bq   = (const float*)d_in[8];
    const float* bv12 = (const float*)d_in[9];
    const float* bo   = (const float*)d_in[10];
    float* out = (float*)d_out;

    proj_kernel<<<dim3(20, 16, 2), 128>>>(x, Wk1, Wk2, Wq, Wv12, bk1, bk2, bq);

    int smem2 = (128*68*2 + MAXT*16 + 128 + 128 + 256 + 64 + 4)*(int)sizeof(float);  // ~80.9 KB
    cudaFuncSetAttribute(attn_kernel, cudaFuncAttributeMaxDynamicSharedMemorySize, smem2);
    attn_kernel<<<dim3(128, 8, 2), 256, smem2>>>(bv12);

    out_kernel<<<dim3(4, 16, 2), 128>>>(Wo, bo, out);
}